// round 1
// baseline (speedup 1.0000x reference)
#include <cuda_runtime.h>
#include <math.h>

#define D_MODEL 1024
#define N_HEADS 16
#define D_HEAD  64
#define D_MLP   4096
#define BATCH   2
#define SEQ     2048
#define MROWS   (BATCH*SEQ)   /* 4096 */

// ---------------- scratch (static device globals; no runtime alloc) ----------
__device__ float g_ln1[MROWS*D_MODEL];
__device__ float g_q  [MROWS*D_MODEL];
__device__ float g_k  [MROWS*D_MODEL];
__device__ float g_v  [MROWS*D_MODEL];
__device__ float g_z  [MROWS*D_MODEL];
__device__ float g_r2 [MROWS*D_MODEL];
__device__ float g_ln2[MROWS*D_MODEL];
__device__ float g_h  [MROWS*D_MLP];

// ---------------- layernorm: one block per row of 1024 ----------------------
__global__ __launch_bounds__(256)
void ln_kernel(const float* __restrict__ x, const float* __restrict__ w,
               const float* __restrict__ b, float* __restrict__ y)
{
    int row = blockIdx.x;
    int tid = threadIdx.x;
    const float4* xr = (const float4*)(x + (long)row * D_MODEL);
    float4 v = xr[tid];
    float s = v.x + v.y + v.z + v.w;

    __shared__ float red[8];
    #pragma unroll
    for (int o = 16; o > 0; o >>= 1) s += __shfl_xor_sync(0xffffffffu, s, o);
    if ((tid & 31) == 0) red[tid >> 5] = s;
    __syncthreads();
    float tot = 0.f;
    #pragma unroll
    for (int i = 0; i < 8; i++) tot += red[i];
    float mean = tot * (1.0f / D_MODEL);

    float dx = v.x - mean, dy = v.y - mean, dz = v.z - mean, dw = v.w - mean;
    float ss = dx*dx + dy*dy + dz*dz + dw*dw;
    __syncthreads();
    #pragma unroll
    for (int o = 16; o > 0; o >>= 1) ss += __shfl_xor_sync(0xffffffffu, ss, o);
    if ((tid & 31) == 0) red[tid >> 5] = ss;
    __syncthreads();
    float tvar = 0.f;
    #pragma unroll
    for (int i = 0; i < 8; i++) tvar += red[i];
    float inv = rsqrtf(tvar * (1.0f / D_MODEL) + 1e-5f);

    float4 wv = ((const float4*)w)[tid];
    float4 bv = ((const float4*)b)[tid];
    float4 o;
    o.x = dx * inv * wv.x + bv.x;
    o.y = dy * inv * wv.y + bv.y;
    o.z = dz * inv * wv.z + bv.z;
    o.w = dw * inv * wv.w + bv.w;
    ((float4*)(y + (long)row * D_MODEL))[tid] = o;
}

// ---------------- generic tiled SGEMM 64x64x16, 4x4 per thread --------------
__device__ __forceinline__ float gelu_f(float x)
{
    const float c = 0.7978845608028654f;
    float x3 = x * x * x;
    return 0.5f * x * (1.0f + tanhf(c * (x + 0.044715f * x3)));
}

#define EPI_NONE        0
#define EPI_RESID       1
#define EPI_GELU_BIAS   2
#define EPI_BIAS_RESID  3

template<int EPI>
__global__ __launch_bounds__(256)
void sgemm(const float* __restrict__ A, const float* __restrict__ B,
           float* __restrict__ C, int K, int lda, int ldb, int ldc,
           long strideB, int strideCn,
           const float* __restrict__ bias, const float* __restrict__ resid)
{
    __shared__ float As[64][17];
    __shared__ float Bs[16][64];

    int ntile = blockIdx.x, mtile = blockIdx.y, z = blockIdx.z;
    const float* Bp = B + (long)z * strideB;
    int cn0 = z * strideCn + ntile * 64;
    int m0  = mtile * 64;

    int tid = threadIdx.x;
    int tx = tid & 15, ty = tid >> 4;

    float acc[4][4];
    #pragma unroll
    for (int i = 0; i < 4; i++)
        #pragma unroll
        for (int j = 0; j < 4; j++) acc[i][j] = 0.f;

    for (int k0 = 0; k0 < K; k0 += 16) {
        // load A tile (64 rows x 16 cols), coalesced
        #pragma unroll
        for (int i = 0; i < 4; i++) {
            int r = (tid >> 4) + 16 * i;
            As[r][tid & 15] = A[(long)(m0 + r) * lda + k0 + (tid & 15)];
        }
        // load B tile (16 rows x 64 cols), coalesced
        #pragma unroll
        for (int i = 0; i < 4; i++) {
            int r = (tid >> 6) + 4 * i;
            Bs[r][tid & 63] = Bp[(long)(k0 + r) * ldb + ntile * 64 + (tid & 63)];
        }
        __syncthreads();

        #pragma unroll
        for (int kk = 0; kk < 16; kk++) {
            float a0 = As[ty * 4 + 0][kk];
            float a1 = As[ty * 4 + 1][kk];
            float a2 = As[ty * 4 + 2][kk];
            float a3 = As[ty * 4 + 3][kk];
            float4 bv = *(const float4*)&Bs[kk][tx * 4];
            acc[0][0] += a0 * bv.x; acc[0][1] += a0 * bv.y; acc[0][2] += a0 * bv.z; acc[0][3] += a0 * bv.w;
            acc[1][0] += a1 * bv.x; acc[1][1] += a1 * bv.y; acc[1][2] += a1 * bv.z; acc[1][3] += a1 * bv.w;
            acc[2][0] += a2 * bv.x; acc[2][1] += a2 * bv.y; acc[2][2] += a2 * bv.z; acc[2][3] += a2 * bv.w;
            acc[3][0] += a3 * bv.x; acc[3][1] += a3 * bv.y; acc[3][2] += a3 * bv.z; acc[3][3] += a3 * bv.w;
        }
        __syncthreads();
    }

    #pragma unroll
    for (int i = 0; i < 4; i++) {
        int m = m0 + ty * 4 + i;
        #pragma unroll
        for (int j = 0; j < 4; j++) {
            int n = cn0 + tx * 4 + j;
            float v = acc[i][j];
            if (EPI == EPI_RESID)      v += resid[(long)m * ldc + n];
            if (EPI == EPI_GELU_BIAS)  v = gelu_f(v + bias[n]);
            if (EPI == EPI_BIAS_RESID) v += bias[n] + resid[(long)m * ldc + n];
            C[(long)m * ldc + n] = v;
        }
    }
}

// ---------------- flash-style causal attention -------------------------------
// Layouts: q/k/v/z all [b, s, h, e] (stride: s->1024, h->64).
// One thread owns one query row. grid = (SEQ/64, N_HEADS, BATCH), 64 threads.
__global__ __launch_bounds__(64)
void attn_kernel(const float* __restrict__ Q, const float* __restrict__ K,
                 const float* __restrict__ V, float* __restrict__ Z)
{
    __shared__ float Ks[64][64];
    __shared__ float Vs[64][64];

    int qt = blockIdx.x, h = blockIdx.y, b = blockIdx.z;
    int tid = threadIdx.x;           // 0..63
    int qg  = qt * 64 + tid;         // global query index

    float qreg[64];
    {
        const float4* qp = (const float4*)(Q + ((long)(b * SEQ + qg)) * D_MODEL + h * D_HEAD);
        #pragma unroll
        for (int d4 = 0; d4 < 16; d4++) {
            float4 t = qp[d4];
            qreg[4*d4+0] = t.x * 0.125f;  // fold 1/sqrt(64)
            qreg[4*d4+1] = t.y * 0.125f;
            qreg[4*d4+2] = t.z * 0.125f;
            qreg[4*d4+3] = t.w * 0.125f;
        }
    }

    float acc[64];
    #pragma unroll
    for (int d = 0; d < 64; d++) acc[d] = 0.f;
    float mrow = -INFINITY, lrow = 0.f;

    for (int kt = 0; kt <= qt; kt++) {
        // cooperative coalesced load of K/V tiles (64 keys x 64 dims)
        const float* Kb = K + ((long)(b * SEQ + kt * 64)) * D_MODEL + h * D_HEAD;
        const float* Vb = V + ((long)(b * SEQ + kt * 64)) * D_MODEL + h * D_HEAD;
        #pragma unroll
        for (int rr = 0; rr < 16; rr++) {
            int row = rr * 4 + (tid >> 4);
            int c4  = (tid & 15) * 4;
            *(float4*)&Ks[row][c4] = *(const float4*)&Kb[(long)row * D_MODEL + c4];
            *(float4*)&Vs[row][c4] = *(const float4*)&Vb[(long)row * D_MODEL + c4];
        }
        __syncthreads();

        int kmax = qg - kt * 64 + 1;
        if (kmax > 64) kmax = 64;

        for (int kk = 0; kk < kmax; kk++) {
            float s0 = 0.f, s1 = 0.f, s2 = 0.f, s3 = 0.f;
            #pragma unroll
            for (int d4 = 0; d4 < 16; d4++) {
                float4 kv = *(const float4*)&Ks[kk][d4 * 4];
                s0 += qreg[4*d4+0] * kv.x;
                s1 += qreg[4*d4+1] * kv.y;
                s2 += qreg[4*d4+2] * kv.z;
                s3 += qreg[4*d4+3] * kv.w;
            }
            float sc = (s0 + s1) + (s2 + s3);

            if (sc <= mrow) {                 // common path: no rescale
                float p = __expf(sc - mrow);
                lrow += p;
                #pragma unroll
                for (int d4 = 0; d4 < 16; d4++) {
                    float4 vv = *(const float4*)&Vs[kk][d4 * 4];
                    acc[4*d4+0] += p * vv.x;
                    acc[4*d4+1] += p * vv.y;
                    acc[4*d4+2] += p * vv.z;
                    acc[4*d4+3] += p * vv.w;
                }
            } else {                          // new max: rescale (p = 1)
                float corr = __expf(mrow - sc);
                mrow = sc;
                lrow = lrow * corr + 1.0f;
                #pragma unroll
                for (int d4 = 0; d4 < 16; d4++) {
                    float4 vv = *(const float4*)&Vs[kk][d4 * 4];
                    acc[4*d4+0] = acc[4*d4+0] * corr + vv.x;
                    acc[4*d4+1] = acc[4*d4+1] * corr + vv.y;
                    acc[4*d4+2] = acc[4*d4+2] * corr + vv.z;
                    acc[4*d4+3] = acc[4*d4+3] * corr + vv.w;
                }
            }
        }
        __syncthreads();
    }

    float invl = 1.0f / lrow;
    float* zp = Z + ((long)(b * SEQ + qg)) * D_MODEL + h * D_HEAD;
    #pragma unroll
    for (int d4 = 0; d4 < 16; d4++) {
        float4 o;
        o.x = acc[4*d4+0] * invl;
        o.y = acc[4*d4+1] * invl;
        o.z = acc[4*d4+2] * invl;
        o.w = acc[4*d4+3] * invl;
        *(float4*)&zp[d4 * 4] = o;
    }
}

// ---------------- host orchestration ----------------------------------------
extern "C" void kernel_launch(void* const* d_in, const int* in_sizes, int n_in,
                              void* d_out, int out_size)
{
    const float* resid = (const float*)d_in[0];
    const float* w_q   = (const float*)d_in[1];
    const float* w_k   = (const float*)d_in[2];
    const float* w_v   = (const float*)d_in[3];
    const float* w_o   = (const float*)d_in[4];
    const float* ln1_w = (const float*)d_in[5];
    const float* ln1_b = (const float*)d_in[6];
    const float* ln2_w = (const float*)d_in[7];
    const float* ln2_b = (const float*)d_in[8];
    const float* w_in  = (const float*)d_in[9];
    const float* b_in  = (const float*)d_in[10];
    const float* w_out = (const float*)d_in[11];
    const float* b_out = (const float*)d_in[12];
    float* out = (float*)d_out;

    float *ln1buf, *qb, *kb, *vb, *zb, *r2, *ln2buf, *hb;
    cudaGetSymbolAddress((void**)&ln1buf, g_ln1);
    cudaGetSymbolAddress((void**)&qb,     g_q);
    cudaGetSymbolAddress((void**)&kb,     g_k);
    cudaGetSymbolAddress((void**)&vb,     g_v);
    cudaGetSymbolAddress((void**)&zb,     g_z);
    cudaGetSymbolAddress((void**)&r2,     g_r2);
    cudaGetSymbolAddress((void**)&ln2buf, g_ln2);
    cudaGetSymbolAddress((void**)&hb,     g_h);

    // 1. ln1 = LN(resid)
    ln_kernel<<<MROWS, 256>>>(resid, ln1_w, ln1_b, ln1buf);

    // 2. q/k/v = ln1 @ w_{q,k,v}[h]  (batched over heads via grid.z)
    sgemm<EPI_NONE><<<dim3(1, 64, 16), 256>>>(ln1buf, w_q, qb,
        D_MODEL, D_MODEL, D_HEAD, D_MODEL, (long)D_MODEL * D_HEAD, D_HEAD, nullptr, nullptr);
    sgemm<EPI_NONE><<<dim3(1, 64, 16), 256>>>(ln1buf, w_k, kb,
        D_MODEL, D_MODEL, D_HEAD, D_MODEL, (long)D_MODEL * D_HEAD, D_HEAD, nullptr, nullptr);
    sgemm<EPI_NONE><<<dim3(1, 64, 16), 256>>>(ln1buf, w_v, vb,
        D_MODEL, D_MODEL, D_HEAD, D_MODEL, (long)D_MODEL * D_HEAD, D_HEAD, nullptr, nullptr);

    // 3. causal flash attention -> z [b,s,h,e]
    attn_kernel<<<dim3(SEQ / 64, N_HEADS, BATCH), 64>>>(qb, kb, vb, zb);

    // 4. r2 = resid + z @ w_o   (w_o flattens to [1024,1024])
    sgemm<EPI_RESID><<<dim3(16, 64, 1), 256>>>(zb, w_o, r2,
        D_MODEL, D_MODEL, D_MODEL, D_MODEL, 0, 0, nullptr, resid);

    // 5. ln2 = LN(r2)
    ln_kernel<<<MROWS, 256>>>(r2, ln2_w, ln2_b, ln2buf);

    // 6. h = gelu(ln2 @ w_in + b_in)
    sgemm<EPI_GELU_BIAS><<<dim3(64, 64, 1), 256>>>(ln2buf, w_in, hb,
        D_MODEL, D_MODEL, D_MLP, D_MLP, 0, 0, b_in, nullptr);

    // 7. out = r2 + h @ w_out + b_out
    sgemm<EPI_BIAS_RESID><<<dim3(16, 64, 1), 256>>>(hb, w_out, out,
        D_MLP, D_MLP, D_MODEL, D_MODEL, 0, 0, b_out, r2);
}

// round 3
// speedup vs baseline: 1.5897x; 1.5897x over previous
#include <cuda_runtime.h>
#include <cuda_bf16.h>
#include <cstdint>
#include <math.h>

#define D_MODEL 1024
#define N_HEADS 16
#define D_HEAD  64
#define D_MLP   4096
#define BATCH   2
#define SEQ     2048
#define MROWS   (BATCH*SEQ)   /* 4096 */

// ---------------------------------------------------------------------------
// scratch (static device globals; no runtime alloc)
// ---------------------------------------------------------------------------
__device__ float          g_qkv [MROWS*3*D_MODEL];        // fp32 q|k|v, ldc=3072
__device__ float          g_r2  [MROWS*D_MODEL];
__device__ __nv_bfloat16  g_ln1h[MROWS*D_MODEL], g_ln1l[MROWS*D_MODEL];
__device__ __nv_bfloat16  g_ln2h[MROWS*D_MODEL], g_ln2l[MROWS*D_MODEL];
__device__ __nv_bfloat16  g_zh  [MROWS*D_MODEL], g_zl  [MROWS*D_MODEL];
__device__ __nv_bfloat16  g_hh  [MROWS*D_MLP],   g_hl  [MROWS*D_MLP];
// transposed+split weights, [N][K] K-major
__device__ __nv_bfloat16  g_Bqkvh[3*D_MODEL*D_MODEL], g_Bqkvl[3*D_MODEL*D_MODEL];
__device__ __nv_bfloat16  g_Boh  [D_MODEL*D_MODEL],   g_Bol  [D_MODEL*D_MODEL];
__device__ __nv_bfloat16  g_Binh [D_MLP*D_MODEL],     g_Binl [D_MLP*D_MODEL];
__device__ __nv_bfloat16  g_Bouth[D_MODEL*D_MLP],     g_Boutl[D_MODEL*D_MLP];

// ---------------------------------------------------------------------------
// helpers
// ---------------------------------------------------------------------------
__device__ __forceinline__ uint32_t smem_to_u32(const void* p) {
    uint32_t a;
    asm("{ .reg .u64 t; cvta.to.shared.u64 t, %1; cvt.u32.u64 %0, t; }" : "=r"(a) : "l"(p));
    return a;
}

__device__ __forceinline__ void cp16(uint32_t s, const void* g) {
    asm volatile("cp.async.cg.shared.global [%0], [%1], 16;" :: "r"(s), "l"(g) : "memory");
}
#define CP_COMMIT()  asm volatile("cp.async.commit_group;" ::: "memory")
#define CP_WAIT1()   asm volatile("cp.async.wait_group 1;" ::: "memory")
#define CP_WAIT0()   asm volatile("cp.async.wait_group 0;" ::: "memory")

__device__ __forceinline__ void ldm_x4(uint32_t* r, uint32_t a) {
    asm volatile("ldmatrix.sync.aligned.m8n8.x4.shared.b16 {%0,%1,%2,%3}, [%4];"
        : "=r"(r[0]), "=r"(r[1]), "=r"(r[2]), "=r"(r[3]) : "r"(a));
}
__device__ __forceinline__ void ldm_x2(uint32_t* r, uint32_t a) {
    asm volatile("ldmatrix.sync.aligned.m8n8.x2.shared.b16 {%0,%1}, [%2];"
        : "=r"(r[0]), "=r"(r[1]) : "r"(a));
}
__device__ __forceinline__ void mma_bf16(float* d, const uint32_t* a, const uint32_t* b) {
    asm volatile("mma.sync.aligned.m16n8k16.row.col.f32.bf16.bf16.f32 "
        "{%0,%1,%2,%3}, {%4,%5,%6,%7}, {%8,%9}, {%0,%1,%2,%3};"
        : "+f"(d[0]), "+f"(d[1]), "+f"(d[2]), "+f"(d[3])
        : "r"(a[0]), "r"(a[1]), "r"(a[2]), "r"(a[3]), "r"(b[0]), "r"(b[1]));
}

__device__ __forceinline__ void split_bf16(float x, __nv_bfloat16& hi, __nv_bfloat16& lo) {
    hi = __float2bfloat16_rn(x);
    lo = __float2bfloat16_rn(x - __bfloat162float(hi));
}

__device__ __forceinline__ float gelu_f(float x) {
    const float c = 0.7978845608028654f;
    float x3 = x * x * x;
    return 0.5f * x * (1.0f + tanhf(c * (x + 0.044715f * x3)));
}

// ---------------------------------------------------------------------------
// layernorm -> split bf16 hi/lo
// ---------------------------------------------------------------------------
__global__ __launch_bounds__(256)
void ln_split_kernel(const float* __restrict__ x, const float* __restrict__ w,
                     const float* __restrict__ b,
                     __nv_bfloat16* __restrict__ yh, __nv_bfloat16* __restrict__ yl)
{
    int row = blockIdx.x;
    int tid = threadIdx.x;
    const float4* xr = (const float4*)(x + (size_t)row * D_MODEL);
    float4 v = xr[tid];
    float s = v.x + v.y + v.z + v.w;

    __shared__ float red[8];
    #pragma unroll
    for (int o = 16; o > 0; o >>= 1) s += __shfl_xor_sync(0xffffffffu, s, o);
    if ((tid & 31) == 0) red[tid >> 5] = s;
    __syncthreads();
    float tot = 0.f;
    #pragma unroll
    for (int i = 0; i < 8; i++) tot += red[i];
    float mean = tot * (1.0f / D_MODEL);

    float dx = v.x - mean, dy = v.y - mean, dz = v.z - mean, dw = v.w - mean;
    float ss = dx*dx + dy*dy + dz*dz + dw*dw;
    __syncthreads();
    #pragma unroll
    for (int o = 16; o > 0; o >>= 1) ss += __shfl_xor_sync(0xffffffffu, ss, o);
    if ((tid & 31) == 0) red[tid >> 5] = ss;
    __syncthreads();
    float tvar = 0.f;
    #pragma unroll
    for (int i = 0; i < 8; i++) tvar += red[i];
    float inv = rsqrtf(tvar * (1.0f / D_MODEL) + 1e-5f);

    float4 wv = ((const float4*)w)[tid];
    float4 bv = ((const float4*)b)[tid];
    float o0 = dx * inv * wv.x + bv.x;
    float o1 = dy * inv * wv.y + bv.y;
    float o2 = dz * inv * wv.z + bv.z;
    float o3 = dw * inv * wv.w + bv.w;

    __nv_bfloat16 h0,h1,h2,h3,l0,l1,l2,l3;
    split_bf16(o0, h0, l0);
    split_bf16(o1, h1, l1);
    split_bf16(o2, h2, l2);
    split_bf16(o3, h3, l3);
    uint2 uh, ul;
    uh.x = ((uint32_t)__bfloat16_as_ushort(h0)) | ((uint32_t)__bfloat16_as_ushort(h1) << 16);
    uh.y = ((uint32_t)__bfloat16_as_ushort(h2)) | ((uint32_t)__bfloat16_as_ushort(h3) << 16);
    ul.x = ((uint32_t)__bfloat16_as_ushort(l0)) | ((uint32_t)__bfloat16_as_ushort(l1) << 16);
    ul.y = ((uint32_t)__bfloat16_as_ushort(l2)) | ((uint32_t)__bfloat16_as_ushort(l3) << 16);
    ((uint2*)(yh + (size_t)row * D_MODEL))[tid] = uh;
    ((uint2*)(yl + (size_t)row * D_MODEL))[tid] = ul;
}

// ---------------------------------------------------------------------------
// weight transpose + split: in [R][C] fp32 -> out [C][R] bf16 hi/lo
// ---------------------------------------------------------------------------
__global__ __launch_bounds__(256)
void transpose_split(const float* __restrict__ in,
                     __nv_bfloat16* __restrict__ ohi, __nv_bfloat16* __restrict__ olo,
                     int R, int C, long inBatch, long outBatch)
{
    __shared__ float s[32][33];
    int tx = threadIdx.x & 31, ty = threadIdx.x >> 5;
    int c0 = blockIdx.x * 32, r0 = blockIdx.y * 32;
    long ib = (long)blockIdx.z * inBatch;
    long ob = (long)blockIdx.z * outBatch;
    #pragma unroll
    for (int i = 0; i < 4; i++)
        s[ty + 8*i][tx] = in[ib + (size_t)(r0 + ty + 8*i) * C + c0 + tx];
    __syncthreads();
    #pragma unroll
    for (int i = 0; i < 4; i++) {
        float x = s[tx][ty + 8*i];
        __nv_bfloat16 hi, lo;
        split_bf16(x, hi, lo);
        size_t idx = ob + (size_t)(c0 + ty + 8*i) * R + r0 + tx;
        ohi[idx] = hi;
        olo[idx] = lo;
    }
}

// ---------------------------------------------------------------------------
// mma.sync split-bf16 GEMM: C[M,N] = A[M,K] @ B[N,K]^T, 3-term compensated
// CTA tile 128x128x32; 8 warps of 64x32; cp.async double-buffer.
// Smem per stage: Ah,Al,Bh,Bl each [128][40] bf16 (pad 32->40 for ldmatrix)
// ---------------------------------------------------------------------------
#define BK      32
#define ROWPAD  40                       /* elements per smem row */
#define ARR_B   (128*ROWPAD*2)           /* 10240 bytes per array */
#define STG_B   (4*ARR_B)                /* 40960 bytes per stage */
#define GEMM_SMEM (2*STG_B)              /* 81920 */

#define EPI_NONE        0
#define EPI_RESID       1
#define EPI_GELU_SPLIT  2
#define EPI_BIAS_RESID  3

template<int EPI>
__global__ __launch_bounds__(256)
void gemm_mma(const __nv_bfloat16* __restrict__ Ah, const __nv_bfloat16* __restrict__ Al,
              const __nv_bfloat16* __restrict__ Bh, const __nv_bfloat16* __restrict__ Bl,
              float* __restrict__ C,
              __nv_bfloat16* __restrict__ Chi, __nv_bfloat16* __restrict__ Clo,
              int K, int ldc,
              const float* __restrict__ bias, const float* __restrict__ resid)
{
    extern __shared__ char smem[];
    const uint32_t sb = smem_to_u32(smem);
    const int tid  = threadIdx.x;
    const int w    = tid >> 5;
    const int lane = tid & 31;
    const int m0 = blockIdx.y * 128;
    const int n0 = blockIdx.x * 128;

    // per-warp tile origin: 2 (M) x 4 (N) warps
    const int wm0 = (w & 1) * 64;
    const int wn0 = (w >> 1) * 32;

    float acc[4][4][4];
    #pragma unroll
    for (int i = 0; i < 4; i++)
        #pragma unroll
        for (int j = 0; j < 4; j++)
            #pragma unroll
            for (int r = 0; r < 4; r++) acc[i][j][r] = 0.f;

    // loader indices: per array, 512 chunks of 16B; thread does chunks tid, tid+256
    const int lrow0 = tid >> 2,  lkc0 = tid & 3;           // chunk tid
    const int lrow1 = (tid + 256) >> 2, lkc1 = (tid + 256) & 3;

    auto load_stage = [&](int slot, int k0) {
        uint32_t st = sb + slot * STG_B;
        // A hi/lo
        {
            size_t g0 = (size_t)(m0 + lrow0) * K + k0 + lkc0 * 8;
            size_t g1 = (size_t)(m0 + lrow1) * K + k0 + lkc1 * 8;
            uint32_t s0 = st + lrow0 * (ROWPAD*2) + lkc0 * 16;
            uint32_t s1 = st + lrow1 * (ROWPAD*2) + lkc1 * 16;
            cp16(s0,           Ah + g0);
            cp16(s1,           Ah + g1);
            cp16(s0 + ARR_B,   Al + g0);
            cp16(s1 + ARR_B,   Al + g1);
        }
        // B hi/lo
        {
            size_t g0 = (size_t)(n0 + lrow0) * K + k0 + lkc0 * 8;
            size_t g1 = (size_t)(n0 + lrow1) * K + k0 + lkc1 * 8;
            uint32_t s0 = st + 2*ARR_B + lrow0 * (ROWPAD*2) + lkc0 * 16;
            uint32_t s1 = st + 2*ARR_B + lrow1 * (ROWPAD*2) + lkc1 * 16;
            cp16(s0,           Bh + g0);
            cp16(s1,           Bh + g1);
            cp16(s0 + ARR_B,   Bl + g0);
            cp16(s1 + ARR_B,   Bl + g1);
        }
    };

    // ldmatrix per-lane base offsets
    const uint32_t aOff = (uint32_t)((wm0 + (lane & 15)) * (ROWPAD*2) + (lane >> 4) * 16);
    const uint32_t bOff = (uint32_t)((wn0 + (lane & 7)) * (ROWPAD*2) + ((lane >> 3) & 1) * 16);

    const int NC = K / BK;
    load_stage(0, 0);
    CP_COMMIT();

    for (int c = 0; c < NC; c++) {
        if (c + 1 < NC) { load_stage((c + 1) & 1, (c + 1) * BK); CP_COMMIT(); CP_WAIT1(); }
        else            { CP_WAIT0(); }
        __syncthreads();

        uint32_t st = sb + (c & 1) * STG_B;
        uint32_t aHi = st + aOff;
        uint32_t aLo = st + ARR_B + aOff;
        uint32_t bHi = st + 2*ARR_B + bOff;
        uint32_t bLo = st + 3*ARR_B + bOff;

        #pragma unroll
        for (int ks = 0; ks < 2; ks++) {
            uint32_t ah[4][4], al[4][4], bh[4][2], bl[4][2];
            #pragma unroll
            for (int mt = 0; mt < 4; mt++) {
                ldm_x4(ah[mt], aHi + mt * 16 * (ROWPAD*2) + ks * 32);
                ldm_x4(al[mt], aLo + mt * 16 * (ROWPAD*2) + ks * 32);
            }
            #pragma unroll
            for (int nt = 0; nt < 4; nt++) {
                ldm_x2(bh[nt], bHi + nt * 8 * (ROWPAD*2) + ks * 32);
                ldm_x2(bl[nt], bLo + nt * 8 * (ROWPAD*2) + ks * 32);
            }
            #pragma unroll
            for (int mt = 0; mt < 4; mt++)
                #pragma unroll
                for (int nt = 0; nt < 4; nt++) {
                    mma_bf16(acc[mt][nt], ah[mt], bh[nt]);
                    mma_bf16(acc[mt][nt], ah[mt], bl[nt]);
                    mma_bf16(acc[mt][nt], al[mt], bh[nt]);
                }
        }
        __syncthreads();
    }

    // ---------------- epilogue ----------------
    #pragma unroll
    for (int mt = 0; mt < 4; mt++) {
        int r0 = m0 + wm0 + mt * 16 + (lane >> 2);
        #pragma unroll
        for (int nt = 0; nt < 4; nt++) {
            int cb = n0 + wn0 + nt * 8 + (lane & 3) * 2;
            float v00 = acc[mt][nt][0], v01 = acc[mt][nt][1];
            float v10 = acc[mt][nt][2], v11 = acc[mt][nt][3];
            if (EPI == EPI_GELU_SPLIT) {
                v00 = gelu_f(v00 + bias[cb]);     v01 = gelu_f(v01 + bias[cb+1]);
                v10 = gelu_f(v10 + bias[cb]);     v11 = gelu_f(v11 + bias[cb+1]);
                __nv_bfloat16 h0,h1,l0,l1;
                split_bf16(v00, h0, l0); split_bf16(v01, h1, l1);
                *(uint32_t*)(Chi + (size_t)r0 * ldc + cb) =
                    ((uint32_t)__bfloat16_as_ushort(h0)) | ((uint32_t)__bfloat16_as_ushort(h1) << 16);
                *(uint32_t*)(Clo + (size_t)r0 * ldc + cb) =
                    ((uint32_t)__bfloat16_as_ushort(l0)) | ((uint32_t)__bfloat16_as_ushort(l1) << 16);
                split_bf16(v10, h0, l0); split_bf16(v11, h1, l1);
                *(uint32_t*)(Chi + (size_t)(r0+8) * ldc + cb) =
                    ((uint32_t)__bfloat16_as_ushort(h0)) | ((uint32_t)__bfloat16_as_ushort(h1) << 16);
                *(uint32_t*)(Clo + (size_t)(r0+8) * ldc + cb) =
                    ((uint32_t)__bfloat16_as_ushort(l0)) | ((uint32_t)__bfloat16_as_ushort(l1) << 16);
            } else {
                if (EPI == EPI_BIAS_RESID) {
                    v00 += bias[cb]; v01 += bias[cb+1];
                    v10 += bias[cb]; v11 += bias[cb+1];
                }
                if (EPI == EPI_RESID || EPI == EPI_BIAS_RESID) {
                    float2 ra = *(const float2*)(resid + (size_t)r0 * ldc + cb);
                    float2 rb = *(const float2*)(resid + (size_t)(r0+8) * ldc + cb);
                    v00 += ra.x; v01 += ra.y; v10 += rb.x; v11 += rb.y;
                }
                float2 o0 = make_float2(v00, v01);
                float2 o1 = make_float2(v10, v11);
                *(float2*)(C + (size_t)r0 * ldc + cb) = o0;
                *(float2*)(C + (size_t)(r0+8) * ldc + cb) = o1;
            }
        }
    }
}

// ---------------------------------------------------------------------------
// flash-style causal attention, fp32, 2 threads per query (split-D)
// QKV layout: [b*SEQ + s][3072]: q at +0, k at +1024, v at +2048, head h at h*64
// ---------------------------------------------------------------------------
__global__ __launch_bounds__(128)
void attn_kernel(const float* __restrict__ QKV,
                 __nv_bfloat16* __restrict__ Zh, __nv_bfloat16* __restrict__ Zl)
{
    __shared__ float Ks[64][64];
    __shared__ float Vs[64][64];

    int qt = blockIdx.x, h = blockIdx.y, b = blockIdx.z;
    int tid = threadIdx.x;
    int q = tid >> 1;
    int half = tid & 1;
    int qg = qt * 64 + q;

    float qreg[32];
    {
        const float4* qp = (const float4*)(QKV + (size_t)(b * SEQ + qg) * 3072 + h * 64 + half * 32);
        #pragma unroll
        for (int d4 = 0; d4 < 8; d4++) {
            float4 t = qp[d4];
            qreg[4*d4+0] = t.x * 0.125f;
            qreg[4*d4+1] = t.y * 0.125f;
            qreg[4*d4+2] = t.z * 0.125f;
            qreg[4*d4+3] = t.w * 0.125f;
        }
    }

    float acc[32];
    #pragma unroll
    for (int d = 0; d < 32; d++) acc[d] = 0.f;
    float mrow = -INFINITY, lrow = 0.f;

    for (int kt = 0; kt <= qt; kt++) {
        const float* Kb = QKV + (size_t)(b * SEQ + kt * 64) * 3072 + 1024 + h * 64;
        const float* Vb = QKV + (size_t)(b * SEQ + kt * 64) * 3072 + 2048 + h * 64;
        #pragma unroll
        for (int i = 0; i < 8; i++) {
            int u = tid + 128 * i;
            int r = u >> 4, c4 = u & 15;
            *(float4*)&Ks[r][c4 * 4] = *(const float4*)(Kb + (size_t)r * 3072 + c4 * 4);
            *(float4*)&Vs[r][c4 * 4] = *(const float4*)(Vb + (size_t)r * 3072 + c4 * 4);
        }
        __syncthreads();

        bool diag = (kt == qt);
        for (int kk = 0; kk < 64; kk++) {
            float s0 = 0.f, s1 = 0.f, s2 = 0.f, s3 = 0.f;
            const float* kr = &Ks[kk][half * 32];
            #pragma unroll
            for (int d4 = 0; d4 < 8; d4++) {
                float4 kv = *(const float4*)(kr + d4 * 4);
                s0 += qreg[4*d4+0] * kv.x;
                s1 += qreg[4*d4+1] * kv.y;
                s2 += qreg[4*d4+2] * kv.z;
                s3 += qreg[4*d4+3] * kv.w;
            }
            float sc = (s0 + s1) + (s2 + s3);
            sc += __shfl_xor_sync(0xffffffffu, sc, 1);
            if (diag && kk > q) sc = -INFINITY;

            const float* vr = &Vs[kk][half * 32];
            if (sc <= mrow) {
                float p = __expf(sc - mrow);
                lrow += p;
                #pragma unroll
                for (int d4 = 0; d4 < 8; d4++) {
                    float4 vv = *(const float4*)(vr + d4 * 4);
                    acc[4*d4+0] += p * vv.x;
                    acc[4*d4+1] += p * vv.y;
                    acc[4*d4+2] += p * vv.z;
                    acc[4*d4+3] += p * vv.w;
                }
            } else {
                float corr = __expf(mrow - sc);
                mrow = sc;
                lrow = lrow * corr + 1.0f;
                #pragma unroll
                for (int d4 = 0; d4 < 8; d4++) {
                    float4 vv = *(const float4*)(vr + d4 * 4);
                    acc[4*d4+0] = acc[4*d4+0] * corr + vv.x;
                    acc[4*d4+1] = acc[4*d4+1] * corr + vv.y;
                    acc[4*d4+2] = acc[4*d4+2] * corr + vv.z;
                    acc[4*d4+3] = acc[4*d4+3] * corr + vv.w;
                }
            }
        }
        __syncthreads();
    }

    float invl = 1.0f / lrow;
    size_t zoff = (size_t)(b * SEQ + qg) * D_MODEL + h * 64 + half * 32;
    #pragma unroll
    for (int j4 = 0; j4 < 8; j4++) {
        float x0 = acc[j4*4+0] * invl;
        float x1 = acc[j4*4+1] * invl;
        float x2 = acc[j4*4+2] * invl;
        float x3 = acc[j4*4+3] * invl;
        __nv_bfloat16 h0,h1,h2,h3,l0,l1,l2,l3;
        split_bf16(x0, h0, l0);
        split_bf16(x1, h1, l1);
        split_bf16(x2, h2, l2);
        split_bf16(x3, h3, l3);
        uint2 uh, ul;
        uh.x = ((uint32_t)__bfloat16_as_ushort(h0)) | ((uint32_t)__bfloat16_as_ushort(h1) << 16);
        uh.y = ((uint32_t)__bfloat16_as_ushort(h2)) | ((uint32_t)__bfloat16_as_ushort(h3) << 16);
        ul.x = ((uint32_t)__bfloat16_as_ushort(l0)) | ((uint32_t)__bfloat16_as_ushort(l1) << 16);
        ul.y = ((uint32_t)__bfloat16_as_ushort(l2)) | ((uint32_t)__bfloat16_as_ushort(l3) << 16);
        *(uint2*)(Zh + zoff + j4*4) = uh;
        *(uint2*)(Zl + zoff + j4*4) = ul;
    }
}

// ---------------------------------------------------------------------------
// host orchestration
// ---------------------------------------------------------------------------
extern "C" void kernel_launch(void* const* d_in, const int* in_sizes, int n_in,
                              void* d_out, int out_size)
{
    const float* resid = (const float*)d_in[0];
    const float* w_q   = (const float*)d_in[1];
    const float* w_k   = (const float*)d_in[2];
    const float* w_v   = (const float*)d_in[3];
    const float* w_o   = (const float*)d_in[4];
    const float* ln1_w = (const float*)d_in[5];
    const float* ln1_b = (const float*)d_in[6];
    const float* ln2_w = (const float*)d_in[7];
    const float* ln2_b = (const float*)d_in[8];
    const float* w_in  = (const float*)d_in[9];
    const float* b_in  = (const float*)d_in[10];
    const float* w_out = (const float*)d_in[11];
    const float* b_out = (const float*)d_in[12];
    float* out = (float*)d_out;

    float *qkv, *r2;
    __nv_bfloat16 *ln1h, *ln1l, *ln2h, *ln2l, *zh, *zl, *hh, *hl;
    __nv_bfloat16 *Bqkvh, *Bqkvl, *Boh, *Bol, *Binh, *Binl, *Bouth, *Boutl;
    cudaGetSymbolAddress((void**)&qkv,   g_qkv);
    cudaGetSymbolAddress((void**)&r2,    g_r2);
    cudaGetSymbolAddress((void**)&ln1h,  g_ln1h);
    cudaGetSymbolAddress((void**)&ln1l,  g_ln1l);
    cudaGetSymbolAddress((void**)&ln2h,  g_ln2h);
    cudaGetSymbolAddress((void**)&ln2l,  g_ln2l);
    cudaGetSymbolAddress((void**)&zh,    g_zh);
    cudaGetSymbolAddress((void**)&zl,    g_zl);
    cudaGetSymbolAddress((void**)&hh,    g_hh);
    cudaGetSymbolAddress((void**)&hl,    g_hl);
    cudaGetSymbolAddress((void**)&Bqkvh, g_Bqkvh);
    cudaGetSymbolAddress((void**)&Bqkvl, g_Bqkvl);
    cudaGetSymbolAddress((void**)&Boh,   g_Boh);
    cudaGetSymbolAddress((void**)&Bol,   g_Bol);
    cudaGetSymbolAddress((void**)&Binh,  g_Binh);
    cudaGetSymbolAddress((void**)&Binl,  g_Binl);
    cudaGetSymbolAddress((void**)&Bouth, g_Bouth);
    cudaGetSymbolAddress((void**)&Boutl, g_Boutl);

    cudaFuncSetAttribute(gemm_mma<EPI_NONE>,       cudaFuncAttributeMaxDynamicSharedMemorySize, GEMM_SMEM);
    cudaFuncSetAttribute(gemm_mma<EPI_RESID>,      cudaFuncAttributeMaxDynamicSharedMemorySize, GEMM_SMEM);
    cudaFuncSetAttribute(gemm_mma<EPI_GELU_SPLIT>, cudaFuncAttributeMaxDynamicSharedMemorySize, GEMM_SMEM);
    cudaFuncSetAttribute(gemm_mma<EPI_BIAS_RESID>, cudaFuncAttributeMaxDynamicSharedMemorySize, GEMM_SMEM);

    // --- weight preparation: transpose + split to [N][K] bf16 hi/lo ---
    transpose_split<<<dim3(2, 32, 16), 256>>>(w_q, Bqkvh,             Bqkvl,             1024, 64, 65536, 65536);
    transpose_split<<<dim3(2, 32, 16), 256>>>(w_k, Bqkvh + 1024*1024, Bqkvl + 1024*1024, 1024, 64, 65536, 65536);
    transpose_split<<<dim3(2, 32, 16), 256>>>(w_v, Bqkvh + 2048*1024, Bqkvl + 2048*1024, 1024, 64, 65536, 65536);
    transpose_split<<<dim3(32, 32, 1),  256>>>(w_o,   Boh,   Bol,   1024, 1024, 0, 0);
    transpose_split<<<dim3(128, 32, 1), 256>>>(w_in,  Binh,  Binl,  1024, 4096, 0, 0);
    transpose_split<<<dim3(32, 128, 1), 256>>>(w_out, Bouth, Boutl, 4096, 1024, 0, 0);

    // --- 1. ln1 = LN(resid) -> bf16 hi/lo ---
    ln_split_kernel<<<MROWS, 256>>>(resid, ln1_w, ln1_b, ln1h, ln1l);

    // --- 2. qkv = ln1 @ Bqkv^T  (N=3072, fp32 out) ---
    gemm_mma<EPI_NONE><<<dim3(24, 32), 256, GEMM_SMEM>>>(
        ln1h, ln1l, Bqkvh, Bqkvl, qkv, nullptr, nullptr, 1024, 3072, nullptr, nullptr);

    // --- 3. attention -> z bf16 hi/lo ---
    attn_kernel<<<dim3(SEQ / 64, N_HEADS, BATCH), 128>>>(qkv, zh, zl);

    // --- 4. r2 = resid + z @ w_o ---
    gemm_mma<EPI_RESID><<<dim3(8, 32), 256, GEMM_SMEM>>>(
        zh, zl, Boh, Bol, r2, nullptr, nullptr, 1024, 1024, nullptr, resid);

    // --- 5. ln2 = LN(r2) -> bf16 hi/lo ---
    ln_split_kernel<<<MROWS, 256>>>(r2, ln2_w, ln2_b, ln2h, ln2l);

    // --- 6. h = gelu(ln2 @ w_in + b_in) -> bf16 hi/lo ---
    gemm_mma<EPI_GELU_SPLIT><<<dim3(32, 32), 256, GEMM_SMEM>>>(
        ln2h, ln2l, Binh, Binl, nullptr, hh, hl, 1024, 4096, b_in, nullptr);

    // --- 7. out = r2 + h @ w_out + b_out ---
    gemm_mma<EPI_BIAS_RESID><<<dim3(8, 32), 256, GEMM_SMEM>>>(
        hh, hl, Bouth, Boutl, out, nullptr, nullptr, 4096, 1024, b_out, r2);
}